// round 12
// baseline (speedup 1.0000x reference)
#include <cuda_runtime.h>

#define H_IN 512
#define W_IN 512
#define HW (H_IN * W_IN)
#define BC 96            // 32 batch * 3 channels
#define BC_PER_THREAD 4
#define BC_CHUNKS (BC / BC_PER_THREAD)   // 24
#define W_SPLIT 352      // warp-uniform region split (multiple of 32)

// max_r = log(norm(512,512)/2 * 2.0) = log(512*sqrt(2))
#define MAX_R 6.58489821531948f
#define PI_F 3.14159265358979323846f

// Warp covers a 4(theta) x 8(r) tile; block of 8 warps covers 8 x 32.
// Grid.x = (512/8)*(512/32) = 1024 blocks.

__global__ __launch_bounds__(256, 7) void logpolar_kernel(
    const float* __restrict__ in, float* __restrict__ out)
{
    const int lane = threadIdx.x & 31;
    const int wp   = threadIdx.x >> 5;        // 0..7
    const int bh   = blockIdx.x >> 4;         // 0..63  (h tile)
    const int bw   = blockIdx.x & 15;         // 0..15  (w tile)

    const int h = (bh << 3) + ((wp >> 2) << 2) + (lane >> 3);  // theta row
    const int w = (bw << 5) + ((wp & 3) << 3) + (lane & 7);    // r col
    const int pix = (h << 9) + w;

    const int bc0 = blockIdx.y * BC_PER_THREAD;

    // Match reference fp32 rounding:
    //   ang    = (2h exact) * pi (1 rnd) * 2^-9 (exact)
    //   radius = exp((w * max_r) (1 rnd) * 2^-9 (exact))
    const float ang = (float)(2 * h) * PI_F * (1.0f / 512.0f);
    const float radius = expf((float)w * MAX_R * (1.0f / 512.0f));

    float s, c;
    sincosf(ang, &s, &c);

    const float X = 256.0f + radius * c;
    const float Y = 256.0f - radius * s;

    const bool mask = (X >= 0.0f) && (X < 512.0f) && (Y >= 0.0f) && (Y < 512.0f);

    float* q = out + (size_t)bc0 * HW + pix;

    if (mask) {
        // trunc toward zero (matches .astype(int32)), then clamp
        int y_down = (int)Y; y_down = min(max(y_down, 0), H_IN - 1);
        int x_down = (int)X; x_down = min(max(x_down, 0), W_IN - 1);
        const int y_up = min(y_down + 1, H_IN - 1);
        const int x_up = min(x_down + 1, W_IN - 1);

        const float yd = Y - (float)y_down;
        const float yu = Y - (float)y_up;
        const float xd = X - (float)x_down;
        const float xu = X - (float)x_up;

        const float dd = yd * yd + xd * xd;
        const float du = yd * yd + xu * xu;
        const float ud = yu * yu + xd * xd;
        const float uu = yu * yu + xu * xu;
        const float inv_total = 1.0f / (dd + du + ud + uu);

        const float w00 = dd * inv_total;
        const float w01 = du * inv_total;
        const float w10 = ud * inv_total;
        const float w11 = uu * inv_total;

        const float* p = in + (size_t)bc0 * HW;
        float2 a[BC_PER_THREAD], b[BC_PER_THREAD];

        if (w >= W_SPLIT) {
            // Scattered region: every lane owns its own sector, so minimize
            // wavefronts: one float4 per row covers both x-taps unless
            // x_down%4==3 (25% of lanes) needs one extra scalar.
            const int  xb     = x_down & ~3;
            const int  idx    = x_down & 3;
            const bool hi     = (idx & 2) != 0;
            const bool lo     = (idx & 1) != 0;
            const bool need_e = (idx == 3) && (x_down != W_IN - 1);

            const int o0 = y_down * W_IN + xb;
            const int o1 = y_up   * W_IN + xb;

            #pragma unroll
            for (int i = 0; i < BC_PER_THREAD; ++i) {
                const float* pi_ = p + (size_t)i * HW;
                const float4 ta = __ldg((const float4*)(pi_ + o0));
                const float4 tb = __ldg((const float4*)(pi_ + o1));
                float ea = ta.w, eb = tb.w;   // idx==3 & right-clamped -> .w
                if (need_e) {
                    ea = __ldg(pi_ + o0 + 4);
                    eb = __ldg(pi_ + o1 + 4);
                }
                const float v0a = hi ? (lo ? ta.w : ta.z) : (lo ? ta.y : ta.x);
                const float v0b = hi ? (lo ? tb.w : tb.z) : (lo ? tb.y : tb.x);
                const float v1a = hi ? (lo ? ea : ta.w) : (lo ? ta.z : ta.y);
                const float v1b = hi ? (lo ? eb : tb.w) : (lo ? tb.z : tb.y);
                a[i] = make_float2(v0a, v1a);
                b[i] = make_float2(v0b, v1b);
            }
        } else {
            // Dense region: lanes share sectors; float2 minimizes return
            // bandwidth. Odd lanes add one scalar per row (mostly shared
            // sectors here, so cheap).
            const int  xb  = x_down & ~1;
            const bool odd = (x_down & 1) != 0;
            const int  o0  = y_down * W_IN + xb;
            const int  o1  = y_up   * W_IN + xb;
            const int  oe0 = y_down * W_IN + x_up;
            const int  oe1 = y_up   * W_IN + x_up;

            #pragma unroll
            for (int i = 0; i < BC_PER_THREAD; ++i) {
                const float* pi_ = p + (size_t)i * HW;
                a[i] = __ldg((const float2*)(pi_ + o0));
                b[i] = __ldg((const float2*)(pi_ + o1));
                if (odd) {
                    a[i].x = a[i].y;  a[i].y = __ldg(pi_ + oe0);
                    b[i].x = b[i].y;  b[i].y = __ldg(pi_ + oe1);
                }
            }
        }

        #pragma unroll
        for (int i = 0; i < BC_PER_THREAD; ++i) {
            q[(size_t)i * HW] = w00 * a[i].x + w01 * a[i].y
                              + w10 * b[i].x + w11 * b[i].y;
        }
    } else {
        #pragma unroll
        for (int i = 0; i < BC_PER_THREAD; ++i) {
            q[(size_t)i * HW] = 0.0f;
        }
    }
}

extern "C" void kernel_launch(void* const* d_in, const int* in_sizes, int n_in,
                              void* d_out, int out_size)
{
    const float* data = (const float*)d_in[0];
    float* out = (float*)d_out;
    dim3 grid(HW / 256, BC_CHUNKS);   // (1024, 24)
    logpolar_kernel<<<grid, 256>>>(data, out);
}

// round 13
// speedup vs baseline: 1.2109x; 1.2109x over previous
#include <cuda_runtime.h>

#define H_IN 512
#define W_IN 512
#define HW (H_IN * W_IN)
#define BC 96            // 32 batch * 3 channels
#define BC_PER_THREAD 6
#define BC_CHUNKS (BC / BC_PER_THREAD)   // 16

// max_r = log(norm(512,512)/2 * 2.0) = log(512*sqrt(2))
#define MAX_R 6.58489821531948f
#define PI_F 3.14159265358979323846f

// Warp covers a 4(theta) x 8(r) tile; block of 8 warps covers 8 x 32.
// Grid.x = (512/8)*(512/32) = 1024 blocks.

__global__ __launch_bounds__(256, 6) void logpolar_kernel(
    const float* __restrict__ in, float* __restrict__ out)
{
    const int lane = threadIdx.x & 31;
    const int wp   = threadIdx.x >> 5;        // 0..7
    const int bh   = blockIdx.x >> 4;         // 0..63  (h tile)
    const int bw   = blockIdx.x & 15;         // 0..15  (w tile)

    const int h = (bh << 3) + ((wp >> 2) << 2) + (lane >> 3);  // theta row
    const int w = (bw << 5) + ((wp & 3) << 3) + (lane & 7);    // r col
    const int pix = (h << 9) + w;

    const int bc0 = blockIdx.y * BC_PER_THREAD;

    // Match reference fp32 rounding:
    //   ang    = (2h exact) * pi (1 rnd) * 2^-9 (exact)
    //   radius = exp((w * max_r) (1 rnd) * 2^-9 (exact))
    const float ang = (float)(2 * h) * PI_F * (1.0f / 512.0f);
    const float radius = expf((float)w * MAX_R * (1.0f / 512.0f));

    float s, c;
    sincosf(ang, &s, &c);

    const float X = 256.0f + radius * c;
    const float Y = 256.0f - radius * s;

    const bool mask = (X >= 0.0f) && (X < 512.0f) && (Y >= 0.0f) && (Y < 512.0f);

    float* q = out + (size_t)bc0 * HW + pix;

    if (mask) {
        // trunc toward zero (matches .astype(int32)), then clamp
        int y_down = (int)Y; y_down = min(max(y_down, 0), H_IN - 1);
        int x_down = (int)X; x_down = min(max(x_down, 0), W_IN - 1);
        const int y_up = min(y_down + 1, H_IN - 1);
        const int x_up = min(x_down + 1, W_IN - 1);

        const float yd = Y - (float)y_down;
        const float yu = Y - (float)y_up;
        const float xd = X - (float)x_down;
        const float xu = X - (float)x_up;

        const float dd = yd * yd + xd * xd;
        const float du = yd * yd + xu * xu;
        const float ud = yu * yu + xd * xd;
        const float uu = yu * yu + xu * xu;
        const float inv_total = 1.0f / (dd + du + ud + uu);

        const float w00 = dd * inv_total;
        const float w01 = du * inv_total;
        const float w10 = ud * inv_total;
        const float w11 = uu * inv_total;

        // Aligned float2 per row covers (x_down, x_down+1) when x_down even.
        const int  xb  = x_down & ~1;
        const bool odd = (x_down & 1) != 0;
        const int  o0  = y_down * W_IN + xb;     // row y_down, aligned pair
        const int  o1  = y_up   * W_IN + xb;     // row y_up,   aligned pair
        const int  oe0 = y_down * W_IN + x_up;   // extra tap when odd
        const int  oe1 = y_up   * W_IN + x_up;

        const float* p = in + (size_t)bc0 * HW;

        // Batch loads; normalize odd lanes in place so the compute loop is
        // a straight FFMA chain on (a.x, a.y, b.x, b.y).
        float2 a[BC_PER_THREAD], b[BC_PER_THREAD];
        #pragma unroll
        for (int i = 0; i < BC_PER_THREAD; ++i) {
            const float* pi_ = p + (size_t)i * HW;
            a[i] = __ldg((const float2*)(pi_ + o0));
            b[i] = __ldg((const float2*)(pi_ + o1));
            if (odd) {
                a[i].x = a[i].y;  a[i].y = __ldg(pi_ + oe0);
                b[i].x = b[i].y;  b[i].y = __ldg(pi_ + oe1);
            }
        }
        #pragma unroll
        for (int i = 0; i < BC_PER_THREAD; ++i) {
            q[(size_t)i * HW] = w00 * a[i].x + w01 * a[i].y
                              + w10 * b[i].x + w11 * b[i].y;
        }
    } else {
        #pragma unroll
        for (int i = 0; i < BC_PER_THREAD; ++i) {
            q[(size_t)i * HW] = 0.0f;
        }
    }
}

extern "C" void kernel_launch(void* const* d_in, const int* in_sizes, int n_in,
                              void* d_out, int out_size)
{
    const float* data = (const float*)d_in[0];
    float* out = (float*)d_out;
    dim3 grid(HW / 256, BC_CHUNKS);   // (1024, 16)
    logpolar_kernel<<<grid, 256>>>(data, out);
}

// round 14
// speedup vs baseline: 1.2496x; 1.0320x over previous
#include <cuda_runtime.h>

#define H_IN 512
#define W_IN 512
#define HW (H_IN * W_IN)
#define BC 96            // 32 batch * 3 channels
#define BC_PER_THREAD 4
#define BC_CHUNKS (BC / BC_PER_THREAD)   // 24

// max_r = log(norm(512,512)/2 * 2.0) = log(512*sqrt(2))
#define MAX_R 6.58489821531948f
#define PI_F 3.14159265358979323846f

// Warp covers a 4(theta) x 8(r) tile. 8192 warp-tiles total.
// Warp->tile mapping is shuffled so each block's 8 warps land on 8 evenly
// spaced r-bands -> every block has identical cost profile (no stragglers).

__global__ __launch_bounds__(256, 8) void logpolar_kernel(
    const float* __restrict__ in, float* __restrict__ out)
{
    const int lane = threadIdx.x & 31;
    const int wp   = threadIdx.x >> 5;        // 0..7
    const int g    = blockIdx.x * 8 + wp;     // global warp-tile id, 0..8191

    const int tr = ((g & 7) << 3) | ((g >> 3) & 7);  // 0..63, spread per block
    const int th = g >> 6;                            // 0..127

    const int h = (th << 2) + (lane >> 3);    // theta row
    const int w = (tr << 3) + (lane & 7);     // r col
    const int pix = (h << 9) + w;

    const int bc0 = blockIdx.y * BC_PER_THREAD;

    // Match reference fp32 rounding:
    //   ang    = (2h exact) * pi (1 rnd) * 2^-9 (exact)
    //   radius = exp((w * max_r) (1 rnd) * 2^-9 (exact))
    const float ang = (float)(2 * h) * PI_F * (1.0f / 512.0f);
    const float radius = expf((float)w * MAX_R * (1.0f / 512.0f));

    float s, c;
    sincosf(ang, &s, &c);

    const float X = 256.0f + radius * c;
    const float Y = 256.0f - radius * s;

    const bool mask = (X >= 0.0f) && (X < 512.0f) && (Y >= 0.0f) && (Y < 512.0f);

    float* q = out + (size_t)bc0 * HW + pix;

    if (mask) {
        // trunc toward zero (matches .astype(int32)), then clamp
        int y_down = (int)Y; y_down = min(max(y_down, 0), H_IN - 1);
        int x_down = (int)X; x_down = min(max(x_down, 0), W_IN - 1);
        const int y_up = min(y_down + 1, H_IN - 1);
        const int x_up = min(x_down + 1, W_IN - 1);

        const float yd = Y - (float)y_down;
        const float yu = Y - (float)y_up;
        const float xd = X - (float)x_down;
        const float xu = X - (float)x_up;

        const float dd = yd * yd + xd * xd;
        const float du = yd * yd + xu * xu;
        const float ud = yu * yu + xd * xd;
        const float uu = yu * yu + xu * xu;
        const float inv_total = 1.0f / (dd + du + ud + uu);

        const float w00 = dd * inv_total;
        const float w01 = du * inv_total;
        const float w10 = ud * inv_total;
        const float w11 = uu * inv_total;

        // Aligned float2 per row covers (x_down, x_down+1) when x_down even.
        const int  xb  = x_down & ~1;
        const bool odd = (x_down & 1) != 0;
        const int  o0  = y_down * W_IN + xb;     // row y_down, aligned pair
        const int  o1  = y_up   * W_IN + xb;     // row y_up,   aligned pair
        const int  oe0 = y_down * W_IN + x_up;   // extra tap when odd
        const int  oe1 = y_up   * W_IN + x_up;

        const float* p = in + (size_t)bc0 * HW;

        // Batch loads; normalize odd lanes in place so the compute loop is
        // a straight FFMA chain on (a.x, a.y, b.x, b.y).
        float2 a[BC_PER_THREAD], b[BC_PER_THREAD];
        #pragma unroll
        for (int i = 0; i < BC_PER_THREAD; ++i) {
            const float* pi_ = p + (size_t)i * HW;
            a[i] = __ldg((const float2*)(pi_ + o0));
            b[i] = __ldg((const float2*)(pi_ + o1));
            if (odd) {
                a[i].x = a[i].y;  a[i].y = __ldg(pi_ + oe0);
                b[i].x = b[i].y;  b[i].y = __ldg(pi_ + oe1);
            }
        }
        #pragma unroll
        for (int i = 0; i < BC_PER_THREAD; ++i) {
            q[(size_t)i * HW] = w00 * a[i].x + w01 * a[i].y
                              + w10 * b[i].x + w11 * b[i].y;
        }
    } else {
        #pragma unroll
        for (int i = 0; i < BC_PER_THREAD; ++i) {
            q[(size_t)i * HW] = 0.0f;
        }
    }
}

extern "C" void kernel_launch(void* const* d_in, const int* in_sizes, int n_in,
                              void* d_out, int out_size)
{
    const float* data = (const float*)d_in[0];
    float* out = (float*)d_out;
    dim3 grid(HW / 256, BC_CHUNKS);   // (1024, 24)
    logpolar_kernel<<<grid, 256>>>(data, out);
}

// round 15
// speedup vs baseline: 1.2890x; 1.0315x over previous
#include <cuda_runtime.h>

#define H_IN 512
#define W_IN 512
#define HW (H_IN * W_IN)
#define BC 96            // 32 batch * 3 channels
#define BC_PER_THREAD 4
#define BC_CHUNKS (BC / BC_PER_THREAD)   // 24

// max_r = log(norm(512,512)/2 * 2.0) = log(512*sqrt(2))
#define MAX_R 6.58489821531948f
#define PI_F 3.14159265358979323846f

// Warp covers a 4(theta) x 8(r) tile; 8192 warp-tiles.
// 128-thread blocks (4 warps) -> 16 blocks/SM at 32 regs: same 64-warp
// ceiling as 256x8, but finer retire/backfill quantum.
// Warp id -> tile: tr fastest (r-band), matching the R7/R9 sweep order.

__global__ __launch_bounds__(128, 16) void logpolar_kernel(
    const float* __restrict__ in, float* __restrict__ out)
{
    const int lane = threadIdx.x & 31;
    const int wp   = threadIdx.x >> 5;        // 0..3
    const int g    = blockIdx.x * 4 + wp;     // global warp-tile id, 0..8191

    const int tr = g & 63;                    // r-band, fastest
    const int th = g >> 6;                    // theta band

    const int h = (th << 2) + (lane >> 3);    // theta row
    const int w = (tr << 3) + (lane & 7);     // r col
    const int pix = (h << 9) + w;

    const int bc0 = blockIdx.y * BC_PER_THREAD;

    // Match reference fp32 rounding:
    //   ang    = (2h exact) * pi (1 rnd) * 2^-9 (exact)
    //   radius = exp((w * max_r) (1 rnd) * 2^-9 (exact))
    const float ang = (float)(2 * h) * PI_F * (1.0f / 512.0f);
    const float radius = expf((float)w * MAX_R * (1.0f / 512.0f));

    float s, c;
    sincosf(ang, &s, &c);

    const float X = 256.0f + radius * c;
    const float Y = 256.0f - radius * s;

    const bool mask = (X >= 0.0f) && (X < 512.0f) && (Y >= 0.0f) && (Y < 512.0f);

    float* q = out + (size_t)bc0 * HW + pix;

    if (mask) {
        // trunc toward zero (matches .astype(int32)), then clamp
        int y_down = (int)Y; y_down = min(max(y_down, 0), H_IN - 1);
        int x_down = (int)X; x_down = min(max(x_down, 0), W_IN - 1);
        const int y_up = min(y_down + 1, H_IN - 1);
        const int x_up = min(x_down + 1, W_IN - 1);

        const float yd = Y - (float)y_down;
        const float yu = Y - (float)y_up;
        const float xd = X - (float)x_down;
        const float xu = X - (float)x_up;

        const float dd = yd * yd + xd * xd;
        const float du = yd * yd + xu * xu;
        const float ud = yu * yu + xd * xd;
        const float uu = yu * yu + xu * xu;
        const float inv_total = 1.0f / (dd + du + ud + uu);

        const float w00 = dd * inv_total;
        const float w01 = du * inv_total;
        const float w10 = ud * inv_total;
        const float w11 = uu * inv_total;

        // Aligned float2 per row covers (x_down, x_down+1) when x_down even.
        const int  xb  = x_down & ~1;
        const bool odd = (x_down & 1) != 0;
        const int  o0  = y_down * W_IN + xb;     // row y_down, aligned pair
        const int  o1  = y_up   * W_IN + xb;     // row y_up,   aligned pair
        const int  oe0 = y_down * W_IN + x_up;   // extra tap when odd
        const int  oe1 = y_up   * W_IN + x_up;

        const float* p = in + (size_t)bc0 * HW;

        // Batch loads; normalize odd lanes in place so the compute loop is
        // a straight FFMA chain on (a.x, a.y, b.x, b.y).
        float2 a[BC_PER_THREAD], b[BC_PER_THREAD];
        #pragma unroll
        for (int i = 0; i < BC_PER_THREAD; ++i) {
            const float* pi_ = p + (size_t)i * HW;
            a[i] = __ldg((const float2*)(pi_ + o0));
            b[i] = __ldg((const float2*)(pi_ + o1));
            if (odd) {
                a[i].x = a[i].y;  a[i].y = __ldg(pi_ + oe0);
                b[i].x = b[i].y;  b[i].y = __ldg(pi_ + oe1);
            }
        }
        #pragma unroll
        for (int i = 0; i < BC_PER_THREAD; ++i) {
            q[(size_t)i * HW] = w00 * a[i].x + w01 * a[i].y
                              + w10 * b[i].x + w11 * b[i].y;
        }
    } else {
        #pragma unroll
        for (int i = 0; i < BC_PER_THREAD; ++i) {
            q[(size_t)i * HW] = 0.0f;
        }
    }
}

extern "C" void kernel_launch(void* const* d_in, const int* in_sizes, int n_in,
                              void* d_out, int out_size)
{
    const float* data = (const float*)d_in[0];
    float* out = (float*)d_out;
    dim3 grid(8192 / 4, BC_CHUNKS);   // (2048, 24)
    logpolar_kernel<<<grid, 128>>>(data, out);
}

// round 17
// speedup vs baseline: 1.2936x; 1.0036x over previous
#include <cuda_runtime.h>

#define H_IN 512
#define W_IN 512
#define HW (H_IN * W_IN)
#define BC 96            // 32 batch * 3 channels
#define BC_PER_THREAD 4
#define BC_CHUNKS (BC / BC_PER_THREAD)   // 24

// max_r = log(norm(512,512)/2 * 2.0) = log(512*sqrt(2))
#define MAX_R 6.58489821531948f
#define PI_F 3.14159265358979323846f

// Input gathers use an L2 evict_last cache policy so the 96MB input stays
// L2-resident while the 100MB output stream flows through evict-first ways.
// Narrow loads need the createpolicy + L2::cache_hint form on sm_103a.
__device__ __forceinline__ unsigned long long mk_evict_last_policy() {
    unsigned long long pol;
    asm("createpolicy.fractional.L2::evict_last.b64 %0, 1.0;" : "=l"(pol));
    return pol;
}
__device__ __forceinline__ float2 ldg_el_f2(const float* p, unsigned long long pol) {
    float2 v;
    asm("ld.global.nc.L2::cache_hint.v2.f32 {%0, %1}, [%2], %3;"
        : "=f"(v.x), "=f"(v.y) : "l"(p), "l"(pol));
    return v;
}
__device__ __forceinline__ float ldg_el_f(const float* p, unsigned long long pol) {
    float v;
    asm("ld.global.nc.L2::cache_hint.f32 %0, [%1], %2;"
        : "=f"(v) : "l"(p), "l"(pol));
    return v;
}

// Warp covers a 4(theta) x 8(r) tile; 8192 warp-tiles.
// 128-thread blocks (4 warps) -> 16 blocks/SM at 32 regs.

__global__ __launch_bounds__(128, 16) void logpolar_kernel(
    const float* __restrict__ in, float* __restrict__ out)
{
    const int lane = threadIdx.x & 31;
    const int wp   = threadIdx.x >> 5;        // 0..3
    const int g    = blockIdx.x * 4 + wp;     // global warp-tile id, 0..8191

    const int tr = g & 63;                    // r-band, fastest
    const int th = g >> 6;                    // theta band

    const int h = (th << 2) + (lane >> 3);    // theta row
    const int w = (tr << 3) + (lane & 7);     // r col
    const int pix = (h << 9) + w;

    const int bc0 = blockIdx.y * BC_PER_THREAD;

    // Match reference fp32 rounding:
    //   ang    = (2h exact) * pi (1 rnd) * 2^-9 (exact)
    //   radius = exp((w * max_r) (1 rnd) * 2^-9 (exact))
    const float ang = (float)(2 * h) * PI_F * (1.0f / 512.0f);
    const float radius = expf((float)w * MAX_R * (1.0f / 512.0f));

    float s, c;
    sincosf(ang, &s, &c);

    const float X = 256.0f + radius * c;
    const float Y = 256.0f - radius * s;

    const bool mask = (X >= 0.0f) && (X < 512.0f) && (Y >= 0.0f) && (Y < 512.0f);

    float* q = out + (size_t)bc0 * HW + pix;

    if (mask) {
        const unsigned long long pol = mk_evict_last_policy();

        // trunc toward zero (matches .astype(int32)), then clamp
        int y_down = (int)Y; y_down = min(max(y_down, 0), H_IN - 1);
        int x_down = (int)X; x_down = min(max(x_down, 0), W_IN - 1);
        const int y_up = min(y_down + 1, H_IN - 1);
        const int x_up = min(x_down + 1, W_IN - 1);

        const float yd = Y - (float)y_down;
        const float yu = Y - (float)y_up;
        const float xd = X - (float)x_down;
        const float xu = X - (float)x_up;

        const float dd = yd * yd + xd * xd;
        const float du = yd * yd + xu * xu;
        const float ud = yu * yu + xd * xd;
        const float uu = yu * yu + xu * xu;
        const float inv_total = 1.0f / (dd + du + ud + uu);

        const float w00 = dd * inv_total;
        const float w01 = du * inv_total;
        const float w10 = ud * inv_total;
        const float w11 = uu * inv_total;

        // Aligned float2 per row covers (x_down, x_down+1) when x_down even.
        const int  xb  = x_down & ~1;
        const bool odd = (x_down & 1) != 0;
        const int  o0  = y_down * W_IN + xb;     // row y_down, aligned pair
        const int  o1  = y_up   * W_IN + xb;     // row y_up,   aligned pair
        const int  oe0 = y_down * W_IN + x_up;   // extra tap when odd
        const int  oe1 = y_up   * W_IN + x_up;

        const float* p = in + (size_t)bc0 * HW;

        // Batch loads; normalize odd lanes in place so the compute loop is
        // a straight FFMA chain on (a.x, a.y, b.x, b.y).
        float2 a[BC_PER_THREAD], b[BC_PER_THREAD];
        #pragma unroll
        for (int i = 0; i < BC_PER_THREAD; ++i) {
            const float* pi_ = p + (size_t)i * HW;
            a[i] = ldg_el_f2(pi_ + o0, pol);
            b[i] = ldg_el_f2(pi_ + o1, pol);
            if (odd) {
                a[i].x = a[i].y;  a[i].y = ldg_el_f(pi_ + oe0, pol);
                b[i].x = b[i].y;  b[i].y = ldg_el_f(pi_ + oe1, pol);
            }
        }
        #pragma unroll
        for (int i = 0; i < BC_PER_THREAD; ++i) {
            q[(size_t)i * HW] = w00 * a[i].x + w01 * a[i].y
                              + w10 * b[i].x + w11 * b[i].y;
        }
    } else {
        #pragma unroll
        for (int i = 0; i < BC_PER_THREAD; ++i) {
            q[(size_t)i * HW] = 0.0f;
        }
    }
}

extern "C" void kernel_launch(void* const* d_in, const int* in_sizes, int n_in,
                              void* d_out, int out_size)
{
    const float* data = (const float*)d_in[0];
    float* out = (float*)d_out;
    dim3 grid(8192 / 4, BC_CHUNKS);   // (2048, 24)
    logpolar_kernel<<<grid, 128>>>(data, out);
}